// round 5
// baseline (speedup 1.0000x reference)
#include <cuda_runtime.h>

// fired[b,s,r] = x[...,i] * x[...,5+j] * x[...,10+k],  r = i*25 + j*5 + k
// Exact zeros in x act as identity (reference: where(rpu==0,1,rpu)).
//
// R4 lesson: latency-bound, not issue-bound (3 kernels w/ different instr
// counts all ~7us; nothing saturated). R5: shorten the critical path:
//   - 512 CTAs x 256 thr, 2 groups of 32 positions per CTA
//   - both groups' LDGs issued at CTA start (2nd DRAM latency hidden)
//   - double-buffered smem, one barrier per stage
//   - phase 2 = R3-style direct product, int offsets (clean LDS)

static constexpr int F    = 15;            // membership functions per position
static constexpr int R    = 125;           // rules per position
static constexpr int G    = 32;            // positions per group
static constexpr int NLD4 = G * F / 4;     // 120 float4 loads per group
static constexpr int NV4G = G * R / 4;     // 1000 float4 outputs per group
static constexpr int SPF  = 4 * F;         // floats per superpos (60)
static constexpr int BUF  = G * F;         // 480 floats per smem buffer

__device__ __forceinline__ float4 fix_zero(float4 v) {
    v.x = (v.x == 0.0f) ? 1.0f : v.x;
    v.y = (v.y == 0.0f) ? 1.0f : v.y;
    v.z = (v.z == 0.0f) ? 1.0f : v.z;
    v.w = (v.w == 0.0f) ? 1.0f : v.w;
    return v;
}

__global__ void __launch_bounds__(256, 8)
rules_fire_v5(const float4* __restrict__ x4, float4* __restrict__ out4,
              int ngroups)
{
    __shared__ float sx[2 * BUF];          // double-buffered membership rows

    const int t  = threadIdx.x;
    const int g0 = 2 * blockIdx.x;
    const int g1 = g0 + 1;
    const bool have_g1 = (g1 < ngroups);

    // ---- Issue BOTH groups' loads up front (MLP=2), fix zeros, stage g0 ----
    float4 r1 = make_float4(1.f, 1.f, 1.f, 1.f);
    if (t < NLD4) {
        float4 r0 = x4[(size_t)g0 * NLD4 + t];
        if (have_g1) r1 = x4[(size_t)g1 * NLD4 + t];
        reinterpret_cast<float4*>(sx)[t] = fix_zero(r0);
    }
    __syncthreads();

    // ---- Loop-invariant rule decomposition (shared by both groups) ----
    int o0[4], o1[4], o2[4];
    int cc = 0, sq = 0;
    if (t < 250) {
        cc = t % 125;                      // float4 chunk within a superpos
        sq = t / 125;                      // which of 2 concurrent superpos
        #pragma unroll
        for (int e = 0; e < 4; e++) {
            const int u  = 4 * cc + e;     // float index within superpos [0,500)
            const int pu = u / R;          // position within superpos 0..3
            const int rr = u - pu * R;     // rule 0..124
            const int b  = sq * SPF + pu * F;
            o0[e] = b + rr / 25;
            o1[e] = b + 5 + (rr / 5) % 5;
            o2[e] = b + 10 + rr % 5;
        }
    }

    // ---- Compute + store group 0; stage group 1 behind it ----
    if (t < 250) {
        float4* o = out4 + (size_t)g0 * NV4G + sq * 125 + cc;
        #pragma unroll
        for (int it = 0; it < 4; it++) {
            const int so = it * 2 * SPF;   // 2 superpos per iteration
            float4 res;
            res.x = sx[o0[0]+so] * sx[o1[0]+so] * sx[o2[0]+so];
            res.y = sx[o0[1]+so] * sx[o1[1]+so] * sx[o2[1]+so];
            res.z = sx[o0[2]+so] * sx[o1[2]+so] * sx[o2[2]+so];
            res.w = sx[o0[3]+so] * sx[o1[3]+so] * sx[o2[3]+so];
            o[it * 250] = res;
        }
    }
    if (t < NLD4)
        reinterpret_cast<float4*>(sx)[BUF / 4 + t] = fix_zero(r1);

    if (!have_g1) return;
    __syncthreads();

    // ---- Compute + store group 1 from the second buffer ----
    if (t < 250) {
        float4* o = out4 + (size_t)g1 * NV4G + sq * 125 + cc;
        #pragma unroll
        for (int it = 0; it < 4; it++) {
            const int so = BUF + it * 2 * SPF;
            float4 res;
            res.x = sx[o0[0]+so] * sx[o1[0]+so] * sx[o2[0]+so];
            res.y = sx[o0[1]+so] * sx[o1[1]+so] * sx[o2[1]+so];
            res.z = sx[o0[2]+so] * sx[o1[2]+so] * sx[o2[2]+so];
            res.w = sx[o0[3]+so] * sx[o1[3]+so] * sx[o2[3]+so];
            o[it * 250] = res;
        }
    }
}

// Scalar fallback for positions past the last full group (unused for B=16,S=2048).
__global__ void rules_fire_tail(const float* __restrict__ x, float* __restrict__ out,
                                int pos0, int npos)
{
    const int pos = pos0 + blockIdx.x;
    if (pos >= npos) return;
    __shared__ float sxt[F + 1];
    const int t = threadIdx.x;
    if (t < F) {
        float v = x[(size_t)pos * F + t];
        sxt[t] = (v == 0.0f) ? 1.0f : v;
    }
    __syncthreads();
    if (t < R) {
        const int i = t / 25, j = (t / 5) % 5, k = t % 5;
        out[(size_t)pos * R + t] = sxt[i] * sxt[5 + j] * sxt[10 + k];
    }
}

extern "C" void kernel_launch(void* const* d_in, const int* in_sizes, int n_in,
                              void* d_out, int out_size)
{
    const float* x = (const float*)d_in[0];   // (B, S, 15) float32
    float* out = (float*)d_out;               // (B, S, 125) float32

    const int npos    = in_sizes[0] / F;      // 32768
    const int ngroups = npos / G;             // 1024
    const int nblocks = (ngroups + 1) / 2;    // 512
    if (nblocks > 0)
        rules_fire_v5<<<nblocks, 256>>>((const float4*)x, (float4*)out, ngroups);

    const int tail = npos - ngroups * G;
    if (tail > 0)
        rules_fire_tail<<<tail, 128>>>(x, out, ngroups * G, npos);
}

// round 7
// speedup vs baseline: 1.0627x; 1.0627x over previous
#include <cuda_runtime.h>
#include <cstdint>

// fired[b,s,r] = x[...,i] * x[...,5+j] * x[...,10+k],  r = i*25 + j*5 + k
// Exact zeros in x act as identity (reference: where(rpu==0,1,rpu)).
//
// R2-R4 plateau diagnosis: cross-CTA L1tex-queue contention from 120
// front-batched LDG.128 per CTA (all warps then barrier-wait; late CTAs'
// loads land deepest -> ~2x spread). R6: stage inputs with ONE
// cp.async.bulk (UBLKCP, no L1tex wavefront queue) + mbarrier, smem-only
// zero-fix pass, then R3's minimal compute body (12 LDS + 8 FMUL + STG.128
// per float4, loop-invariant int offsets).

static constexpr int F     = 15;            // membership functions per position
static constexpr int R     = 125;           // rules per position
static constexpr int G     = 32;            // positions per CTA
static constexpr int BYTES = G * F * 4;     // 1920 B staged per CTA (16B-mult)
static constexpr int SPF   = 4 * F;         // floats per superpos (60)
static constexpr int NV4G  = G * R / 4;     // 1000 float4 outputs per CTA

__device__ __forceinline__ uint32_t smem_u32(const void* p) {
    uint32_t a;
    asm("{ .reg .u64 t; cvta.to.shared.u64 t, %1; cvt.u32.u64 %0, t; }"
        : "=r"(a) : "l"(p));
    return a;
}

__global__ void __launch_bounds__(256, 8)
rules_fire_v6(const float* __restrict__ x, float4* __restrict__ out4)
{
    __shared__ __align__(16) float sx[G * F];     // 480 floats
    __shared__ __align__(8)  unsigned long long mbar;

    const int t   = threadIdx.x;
    const int grp = blockIdx.x;
    const uint32_t mb = smem_u32(&mbar);

    // ---- One bulk copy stages the whole CTA input (no per-thread LDGs) ----
    if (t == 0)
        asm volatile("mbarrier.init.shared.b64 [%0], 1;" :: "r"(mb) : "memory");
    __syncthreads();                               // init visible to waiters
    if (t == 0) {
        asm volatile("mbarrier.arrive.expect_tx.shared.b64 _, [%0], %1;"
                     :: "r"(mb), "r"(BYTES) : "memory");
        asm volatile(
            "cp.async.bulk.shared::cta.global.mbarrier::complete_tx::bytes "
            "[%0], [%1], %2, [%3];"
            :: "r"(smem_u32(sx)), "l"(x + (size_t)grp * G * F),
               "r"(BYTES), "r"(mb) : "memory");
    }

    // ---- Loop-invariant rule decomposition while the copy is in flight ----
    int o0[4], o1[4], o2[4];
    int cc = 0, sq = 0;
    if (t < 250) {
        cc = t % 125;                      // float4 chunk within a superpos
        sq = t / 125;                      // which of 2 concurrent superpos
        #pragma unroll
        for (int e = 0; e < 4; e++) {
            const int u  = 4 * cc + e;     // float index within superpos [0,500)
            const int pu = u / R;          // position within superpos 0..3
            const int rr = u - pu * R;     // rule 0..124
            const int b  = sq * SPF + pu * F;
            o0[e] = b + rr / 25;
            o1[e] = b + 5 + (rr / 5) % 5;
            o2[e] = b + 10 + rr % 5;
        }
    }

    // ---- Wait for the bulk copy (acquire) ----
    {
        uint32_t done;
        asm volatile(
            "{ .reg .pred p; mbarrier.try_wait.parity.acquire.cta.shared::cta.b64 p, [%1], 0; "
            "selp.b32 %0, 1, 0, p; }"
            : "=r"(done) : "r"(mb) : "memory");
        if (!done) {
            asm volatile(
                "{ .reg .pred P; L%=: mbarrier.try_wait.parity.acquire.cta.shared::cta.b64 P, [%0], 0, 0x989680; "
                "@P bra D%=; bra L%=; D%=: }"
                :: "r"(mb) : "memory");
        }
    }

    // ---- smem-only zero->1 fixup pass ----
    if (t < G * F / 4) {
        float4 v = reinterpret_cast<float4*>(sx)[t];
        v.x = (v.x == 0.0f) ? 1.0f : v.x;
        v.y = (v.y == 0.0f) ? 1.0f : v.y;
        v.z = (v.z == 0.0f) ? 1.0f : v.z;
        v.w = (v.w == 0.0f) ? 1.0f : v.w;
        reinterpret_cast<float4*>(sx)[t] = v;
    }
    __syncthreads();

    // ---- Compute: 12 LDS + 8 FMUL + 1 STG.128 per float4 ----
    if (t < 250) {
        float4* o = out4 + (size_t)grp * NV4G + sq * 125 + cc;
        #pragma unroll
        for (int it = 0; it < 4; it++) {
            const int so = it * 2 * SPF;   // 2 superpos per iteration
            float4 res;
            res.x = sx[o0[0]+so] * sx[o1[0]+so] * sx[o2[0]+so];
            res.y = sx[o0[1]+so] * sx[o1[1]+so] * sx[o2[1]+so];
            res.z = sx[o0[2]+so] * sx[o1[2]+so] * sx[o2[2]+so];
            res.w = sx[o0[3]+so] * sx[o1[3]+so] * sx[o2[3]+so];
            o[it * 250] = res;
        }
    }
}

// Scalar fallback for positions past the last full group (unused for B=16,S=2048).
__global__ void rules_fire_tail(const float* __restrict__ x, float* __restrict__ out,
                                int pos0, int npos)
{
    const int pos = pos0 + blockIdx.x;
    if (pos >= npos) return;
    __shared__ float sxt[F + 1];
    const int t = threadIdx.x;
    if (t < F) {
        float v = x[(size_t)pos * F + t];
        sxt[t] = (v == 0.0f) ? 1.0f : v;
    }
    __syncthreads();
    if (t < R) {
        const int i = t / 25, j = (t / 5) % 5, k = t % 5;
        out[(size_t)pos * R + t] = sxt[i] * sxt[5 + j] * sxt[10 + k];
    }
}

extern "C" void kernel_launch(void* const* d_in, const int* in_sizes, int n_in,
                              void* d_out, int out_size)
{
    const float* x = (const float*)d_in[0];   // (B, S, 15) float32
    float* out = (float*)d_out;               // (B, S, 125) float32

    const int npos    = in_sizes[0] / F;      // 32768
    const int ngroups = npos / G;             // 1024
    if (ngroups > 0)
        rules_fire_v6<<<ngroups, 256>>>(x, (float4*)out);

    const int tail = npos - ngroups * G;
    if (tail > 0)
        rules_fire_tail<<<tail, 128>>>(x, out, ngroups * G, npos);
}